// round 3
// baseline (speedup 1.0000x reference)
#include <cuda_runtime.h>
#include <cuda_bf16.h>
#include <cstdint>
#include <math.h>

#define S_LEN 4096
#define BATCH 64
#define HSZ   256
#define MROWS (BATCH * S_LEN)   // 262144

// ---------------- device scratch (allocation-free rule) ----------------
__device__ float g_s [(size_t)MROWS * 128];           // s = event@Ve
__device__ float g_x [(size_t)MROWS * 128];           // x
__device__ float g_u [(size_t)MROWS * 128];           // tanh(s@Wef1+bef1)
__device__ float g_xw[(size_t)MROWS * 1024];          // [b][s][4HS] (bias baked in)
__device__ float g_j [(size_t)MROWS * HSZ];           // [b][s][HS]
__device__ float g_h [2 * BATCH * HSZ];               // double-buffered h
__device__ unsigned g_bar[16 * 32];                   // per-group barrier (padded)

__device__ __forceinline__ float sigf(float x) { return 1.0f / (1.0f + expf(-x)); }

// ---------------- init: zero barriers, h[buf0] = h0 ----------------
__global__ void k_init(const float* __restrict__ h0) {
    int tid = threadIdx.x;
    if (blockIdx.x == 0)
        for (int i = tid; i < 16 * 32; i += 256) g_bar[i] = 0u;
    int base = blockIdx.x * 1024;
    for (int i = tid; i < 1024; i += 256) g_h[base + i] = h0[base + i];
}

// ---------------- embeddings: s = ev@Ve ; x = s + 2*(vc@Vc + tanh(vn@Vn)) --
// tile: 32 rows x 128 cols, 256 threads, thread = 2 rows x 8 cols
__global__ void __launch_bounds__(256, 1)
k_embed(const float* __restrict__ ev, const float* __restrict__ vc,
        const float* __restrict__ vn, const float* __restrict__ Ve,
        const float* __restrict__ Vc, const float* __restrict__ Vn) {
    extern __shared__ float sm[];
    float* wE  = sm;                 // [64][128]
    float* wC  = sm + 64 * 128;      // [32][128]
    float* wN  = sm + 96 * 128;      // [16][128]
    float* ie  = sm + 112 * 128;     // [32][64]
    float* ic  = ie + 32 * 64;       // [32][32]
    float* inn = ic + 32 * 32;       // [32][16]
    int tid = threadIdx.x;
    size_t rb = (size_t)blockIdx.x * 32;

    for (int i = tid; i < 2048; i += 256) ((float4*)wE)[i]  = ((const float4*)Ve)[i];
    for (int i = tid; i < 1024; i += 256) ((float4*)wC)[i]  = ((const float4*)Vc)[i];
    for (int i = tid; i < 512;  i += 256) ((float4*)wN)[i]  = ((const float4*)Vn)[i];
    for (int i = tid; i < 512;  i += 256) ((float4*)ie)[i]  = ((const float4*)(ev + rb * 64))[i];
    for (int i = tid; i < 256;  i += 256) ((float4*)ic)[i]  = ((const float4*)(vc + rb * 32))[i];
    for (int i = tid; i < 128;  i += 256) ((float4*)inn)[i] = ((const float4*)(vn + rb * 16))[i];
    __syncthreads();

    int ty = tid >> 4, tx = tid & 15;   // rows ty*2+{0,1}, cols tx*8+{0..7}
    float sa[2][8], ta[2][8], xa[2][8];
    #pragma unroll
    for (int r = 0; r < 2; r++)
        #pragma unroll
        for (int j = 0; j < 8; j++) { sa[r][j] = 0.f; ta[r][j] = 0.f; }

    #pragma unroll 4
    for (int k = 0; k < 64; k++) {
        float a0 = ie[(ty * 2) * 64 + k], a1 = ie[(ty * 2 + 1) * 64 + k];
        const float* wr = wE + k * 128 + tx * 8;
        float4 w0 = *(const float4*)wr, w1 = *(const float4*)(wr + 4);
        float w[8] = {w0.x, w0.y, w0.z, w0.w, w1.x, w1.y, w1.z, w1.w};
        #pragma unroll
        for (int j = 0; j < 8; j++) { sa[0][j] += a0 * w[j]; sa[1][j] += a1 * w[j]; }
    }
    #pragma unroll 4
    for (int k = 0; k < 32; k++) {
        float a0 = ic[(ty * 2) * 32 + k], a1 = ic[(ty * 2 + 1) * 32 + k];
        const float* wr = wC + k * 128 + tx * 8;
        float4 w0 = *(const float4*)wr, w1 = *(const float4*)(wr + 4);
        float w[8] = {w0.x, w0.y, w0.z, w0.w, w1.x, w1.y, w1.z, w1.w};
        #pragma unroll
        for (int j = 0; j < 8; j++) { ta[0][j] += a0 * w[j]; ta[1][j] += a1 * w[j]; }
    }
    #pragma unroll
    for (int r = 0; r < 2; r++)
        #pragma unroll
        for (int j = 0; j < 8; j++) { xa[r][j] = 2.f * ta[r][j]; ta[r][j] = 0.f; }
    #pragma unroll 4
    for (int k = 0; k < 16; k++) {
        float a0 = inn[(ty * 2) * 16 + k], a1 = inn[(ty * 2 + 1) * 16 + k];
        const float* wr = wN + k * 128 + tx * 8;
        float4 w0 = *(const float4*)wr, w1 = *(const float4*)(wr + 4);
        float w[8] = {w0.x, w0.y, w0.z, w0.w, w1.x, w1.y, w1.z, w1.w};
        #pragma unroll
        for (int j = 0; j < 8; j++) { ta[0][j] += a0 * w[j]; ta[1][j] += a1 * w[j]; }
    }
    #pragma unroll
    for (int r = 0; r < 2; r++) {
        size_t row = rb + ty * 2 + r;
        float o[8];
        #pragma unroll
        for (int j = 0; j < 8; j++) o[j] = sa[r][j] + xa[r][j] + 2.f * tanhf(ta[r][j]);
        float* sp = g_s + row * 128 + tx * 8;
        float* xp = g_x + row * 128 + tx * 8;
        *(float4*)sp       = make_float4(sa[r][0], sa[r][1], sa[r][2], sa[r][3]);
        *(float4*)(sp + 4) = make_float4(sa[r][4], sa[r][5], sa[r][6], sa[r][7]);
        *(float4*)xp       = make_float4(o[0], o[1], o[2], o[3]);
        *(float4*)(xp + 4) = make_float4(o[4], o[5], o[6], o[7]);
    }
}

// ---------------- generic K=128 GEMM: out = act(A@W + bias) ----------------
// tile 64x64, 256 threads (16x16), thread = 4x4, K staged fully in smem
__global__ void __launch_bounds__(256)
k_gemm(const float* __restrict__ A, const float* __restrict__ W,
       const float* __restrict__ bias, float* __restrict__ out,
       int N, int act) {
    extern __shared__ float sm[];
    float* As = sm;            // [64][128]
    float* Ws = sm + 64 * 128; // [128][64]
    int tid = threadIdx.x;
    const float4* A4 = (const float4*)A;
    const float4* W4 = (const float4*)W;
    // load A tile
    for (int i = tid; i < 2048; i += 256)
        ((float4*)As)[i] = A4[((size_t)blockIdx.x * 64 + (i >> 5)) * 32 + (i & 31)];
    // load W tile
    for (int i = tid; i < 2048; i += 256)
        ((float4*)Ws)[i] = W4[(size_t)(i >> 4) * (N >> 2) + blockIdx.y * 16 + (i & 15)];
    __syncthreads();

    int ty = tid >> 4, tx = tid & 15;
    int r0 = ty * 4, c0 = tx * 4;
    float acc[4][4];
    #pragma unroll
    for (int r = 0; r < 4; r++)
        #pragma unroll
        for (int c = 0; c < 4; c++) acc[r][c] = 0.f;

    #pragma unroll 8
    for (int kk = 0; kk < 128; kk += 4) {
        float4 av[4], wv[4];
        #pragma unroll
        for (int r = 0; r < 4; r++) av[r] = *(const float4*)&As[(r0 + r) * 128 + kk];
        #pragma unroll
        for (int i = 0; i < 4; i++) wv[i] = *(const float4*)&Ws[(kk + i) * 64 + c0];
        #pragma unroll
        for (int r = 0; r < 4; r++) {
            acc[r][0] += av[r].x * wv[0].x + av[r].y * wv[1].x + av[r].z * wv[2].x + av[r].w * wv[3].x;
            acc[r][1] += av[r].x * wv[0].y + av[r].y * wv[1].y + av[r].z * wv[2].y + av[r].w * wv[3].y;
            acc[r][2] += av[r].x * wv[0].z + av[r].y * wv[1].z + av[r].z * wv[2].z + av[r].w * wv[3].z;
            acc[r][3] += av[r].x * wv[0].w + av[r].y * wv[1].w + av[r].z * wv[2].w + av[r].w * wv[3].w;
        }
    }

    int colg = blockIdx.y * 64 + c0;
    float4 bv = *(const float4*)&bias[colg];
    #pragma unroll
    for (int r = 0; r < 4; r++) {
        size_t rg = (size_t)blockIdx.x * 64 + r0 + r;
        float v[4] = {acc[r][0] + bv.x, acc[r][1] + bv.y, acc[r][2] + bv.z, acc[r][3] + bv.w};
        if (act == 1) {
            #pragma unroll
            for (int c = 0; c < 4; c++) v[c] = tanhf(v[c]);
        } else if (act == 2) {
            #pragma unroll
            for (int c = 0; c < 4; c++) v[c] = sigf(v[c]);
        }
        *(float4*)&out[rg * N + colg] = make_float4(v[0], v[1], v[2], v[3]);
    }
}

// ---------------- recurrence: 128 CTAs = 16 groups x 8 col-slices ----------
// group g owns batch rows 4g..4g+3; slot c owns units 32c..32c+31 (all 4 gates)
__global__ void __launch_bounds__(256, 1)
k_recur(const float* __restrict__ c0, const float* __restrict__ Wh,
        const float* __restrict__ Wc) {
    extern __shared__ float sm[];
    float* whs = sm;             // [256][128]  Wh slice
    float* hs  = sm + 32768;     // [4][256]    staged h
    float* pb  = hs + 1024;      // [4][128]    split-k partials
    float* gsm = pb + 512;       // [4][128]    gate sums
    int tid   = threadIdx.x;
    int grp   = blockIdx.x >> 3;
    int cslot = blockIdx.x & 7;

    for (int i = tid; i < 32768; i += 256) {
        int k = i >> 7, col = i & 127, q = col >> 5, ul = col & 31;
        whs[i] = Wh[k * 1024 + q * 256 + cslot * 32 + ul];
    }

    int col = tid & 127, kh = tid >> 7;       // GEMV role
    int gq = col >> 5, gul = col & 31;
    int gcol = gq * 256 + cslot * 32 + gul;   // global gate column

    int erow = tid >> 5, eul = tid & 31;      // elementwise role (tid<128)
    int egu  = cslot * 32 + eul;              // global unit
    float c_st = 0.f, wc0 = 0.f, wc1 = 0.f, wc2 = 0.f;
    if (tid < 128) {
        c_st = c0[(grp * 4 + erow) * 256 + egu];
        wc0 = Wc[egu]; wc1 = Wc[256 + egu]; wc2 = Wc[512 + egu];
    }
    __syncthreads();

    for (int t = 0; t < 4096; t++) {
        int p = t & 1;
        // prefetch xw (+bias baked in) and j for this step
        float xw0 = 0.f, xw1 = 0.f, xw2 = 0.f, xw3 = 0.f, jv = 0.f;
        if (kh == 0) {
            size_t xb = ((size_t)(grp * 4) * 4096 + t) * 1024 + gcol;
            xw0 = __ldg(g_xw + xb);
            xw1 = __ldg(g_xw + xb + 4096 * 1024);
            xw2 = __ldg(g_xw + xb + 2u * 4096 * 1024);
            xw3 = __ldg(g_xw + xb + 3u * 4096 * 1024);
        }
        if (tid < 128)
            jv = __ldg(g_j + ((size_t)(grp * 4 + erow) * 4096 + t) * 256 + egu);

        // stage h for this step
        ((float4*)hs)[tid] = ((const float4*)(g_h + p * 16384 + grp * 1024))[tid];
        __syncthreads();

        // GEMV: 4 rows x 1 col, half of K per thread
        float a0 = kh ? 0.f : xw0;
        float a1 = kh ? 0.f : xw1;
        float a2 = kh ? 0.f : xw2;
        float a3 = kh ? 0.f : xw3;
        int k0 = kh * 128;
        #pragma unroll 8
        for (int kk = 0; kk < 128; kk += 4) {
            float4 h0 = *(const float4*)&hs[0 * 256 + k0 + kk];
            float4 h1 = *(const float4*)&hs[1 * 256 + k0 + kk];
            float4 h2 = *(const float4*)&hs[2 * 256 + k0 + kk];
            float4 h3 = *(const float4*)&hs[3 * 256 + k0 + kk];
            const float* wp = whs + (k0 + kk) * 128 + col;
            float w0 = wp[0], w1 = wp[128], w2 = wp[256], w3 = wp[384];
            a0 += h0.x * w0 + h0.y * w1 + h0.z * w2 + h0.w * w3;
            a1 += h1.x * w0 + h1.y * w1 + h1.z * w2 + h1.w * w3;
            a2 += h2.x * w0 + h2.y * w1 + h2.z * w2 + h2.w * w3;
            a3 += h3.x * w0 + h3.y * w1 + h3.z * w2 + h3.w * w3;
        }
        if (kh) {
            pb[col] = a0; pb[128 + col] = a1; pb[256 + col] = a2; pb[384 + col] = a3;
        }
        __syncthreads();
        if (!kh) {
            gsm[col]       = a0 + pb[col];
            gsm[128 + col] = a1 + pb[128 + col];
            gsm[256 + col] = a2 + pb[256 + col];
            gsm[384 + col] = a3 + pb[384 + col];
        }
        __syncthreads();

        // elementwise LSTM update (threads 0..127)
        if (tid < 128) {
            float G0 = gsm[erow * 128 + eul];
            float G1 = gsm[erow * 128 + 32 + eul];
            float G2 = gsm[erow * 128 + 64 + eul];
            float G3 = gsm[erow * 128 + 96 + eul];
            float cc = c_st;
            float iv = sigf(G0 + cc * wc0);
            float fv = sigf(G1 + cc * wc1);
            float gv = tanhf(G2);
            float ov = sigf(G3 + cc * wc2);
            float chat = fv * cc + iv * gv;
            float cn = jv * chat + (1.f - jv) * cc;
            float hh = ov * tanhf(chat);
            float hprev = hs[erow * 256 + egu];
            float hn = jv * hh + (1.f - jv) * hprev;
            c_st = cn;
            g_h[(1 - p) * 16384 + (grp * 4 + erow) * 256 + egu] = hn;
        }
        __threadfence();
        __syncthreads();
        if (tid == 0) {
            atomicAdd(&g_bar[grp * 32], 1u);
            unsigned target = 8u * (unsigned)(t + 1);
            unsigned v;
            do {
                asm volatile("ld.global.acquire.gpu.u32 %0, [%1];"
                             : "=r"(v) : "l"(g_bar + grp * 32));
            } while (v < target);
        }
        __syncthreads();
    }
}

// ---------------- final: out = h_T @ Wlin + blin ----------------
__global__ void k_final(const float* __restrict__ Wlin,
                        const float* __restrict__ blin, float* __restrict__ out) {
    __shared__ float hsm[256];
    int b = blockIdx.x, d = threadIdx.x;   // 64 threads
    for (int i = d; i < 256; i += 64) hsm[i] = g_h[b * 256 + i];  // final h in buf 0
    __syncthreads();
    float acc = blin[d];
    #pragma unroll 8
    for (int k = 0; k < 256; k++) acc += hsm[k] * Wlin[k * 64 + d];
    out[b * 64 + d] = acc;
}

// ---------------- launcher ----------------
extern "C" void kernel_launch(void* const* d_in, const int* in_sizes, int n_in,
                              void* d_out, int out_size) {
    (void)in_sizes; (void)n_in; (void)out_size;
    const float* ev   = (const float*)d_in[0];
    const float* vc   = (const float*)d_in[2];
    const float* vn   = (const float*)d_in[3];
    const float* h0   = (const float*)d_in[4];
    const float* c0   = (const float*)d_in[5];
    const float* Wx   = (const float*)d_in[6];
    const float* Wh   = (const float*)d_in[7];
    const float* Wc   = (const float*)d_in[8];
    const float* bias = (const float*)d_in[9];
    const float* Ve   = (const float*)d_in[10];
    const float* Vc   = (const float*)d_in[11];
    const float* Vn   = (const float*)d_in[12];
    const float* Wlin = (const float*)d_in[13];
    const float* blin = (const float*)d_in[14];
    const float* Wef1 = (const float*)d_in[15];
    const float* bef1 = (const float*)d_in[16];
    const float* Wef3 = (const float*)d_in[17];
    const float* bef3 = (const float*)d_in[18];
    float* out = (float*)d_out;

    cudaFuncSetAttribute(k_embed, cudaFuncAttributeMaxDynamicSharedMemorySize, 71680);
    cudaFuncSetAttribute(k_gemm,  cudaFuncAttributeMaxDynamicSharedMemorySize, 65536);
    cudaFuncSetAttribute(k_recur, cudaFuncAttributeMaxDynamicSharedMemorySize, 139264);

    void *ps, *px, *pu, *pxw, *pj;
    cudaGetSymbolAddress(&ps,  g_s);
    cudaGetSymbolAddress(&px,  g_x);
    cudaGetSymbolAddress(&pu,  g_u);
    cudaGetSymbolAddress(&pxw, g_xw);
    cudaGetSymbolAddress(&pj,  g_j);

    k_init<<<16, 256>>>(h0);
    k_embed<<<MROWS / 32, 256, 71680>>>(ev, vc, vn, Ve, Vc, Vn);
    // xW = x @ Wx + bias            [M,1024]
    k_gemm<<<dim3(MROWS / 64, 16), 256, 65536>>>((const float*)px, Wx, bias,
                                                 (float*)pxw, 1024, 0);
    // u = tanh(s @ Wef1 + bef1)     [M,128]
    k_gemm<<<dim3(MROWS / 64, 2), 256, 65536>>>((const float*)ps, Wef1, bef1,
                                                (float*)pu, 128, 1);
    // j = sigmoid(u @ Wef3 + bef3)  [M,256]
    k_gemm<<<dim3(MROWS / 64, 4), 256, 65536>>>((const float*)pu, Wef3, bef3,
                                                (float*)pj, 256, 2);
    k_recur<<<128, 256, 139264>>>(c0, Wh, Wc);
    k_final<<<64, 64>>>(Wlin, blin, out);
}